// round 6
// baseline (speedup 1.0000x reference)
#include <cuda_runtime.h>
#include <cuda_bf16.h>
#include <math.h>
#include <stdint.h>

// ---------------------------------------------------------------------------
// MultiHeadAttention B=2, S=1024, D=1024 (effective 64 heads x dim 16).
// Legacy mma.sync (HMMA) only -- tcgen05 PTX is rejected at compute_103.
//  0) split_kernel : X inputs and W -> planar hi/lo bf16
//  1) qkv GEMMs    : m16n8k16 bf16, 3-MMA hi/lo split, cp.async + ldmatrix,
//                    epilogue writes q/k/v directly as hi/lo bf16
//  2) attention    : flash-style, ldmatrix B-frags, single-pass softmax,
//                    ctx written as hi/lo bf16
//  3) out GEMM     : same body, fp32 epilogue + bias -> d_out
// Split product: D += Ah*Bh + Ah*Bl + Al*Bh (residual ~2^-16 per product).
// ---------------------------------------------------------------------------

#define BDIM   2
#define SEQ    1024
#define DMODEL 1024
#define MROWS  (BDIM * SEQ)
#define NHEADS 64
#define EDIM   16

#define XW (MROWS * DMODEL / 2)    // words per X-sized bf16 plane (1M)
#define WW (DMODEL * DMODEL / 2)   // words per W-sized bf16 plane (512K)

__device__ unsigned g_xh[3 * XW], g_xl[3 * XW];
__device__ unsigned g_wh[4 * WW], g_wl[4 * WW];
__device__ unsigned g_qh[XW], g_ql[XW];
__device__ unsigned g_kh[XW], g_kl[XW];
__device__ unsigned g_vh[XW], g_vl[XW];
__device__ unsigned g_ch[XW], g_cl[XW];

// ---------------------------------------------------------------------------
// helpers
// ---------------------------------------------------------------------------
__device__ __forceinline__ unsigned packbf(float x, float y) {
    __nv_bfloat162 h = __float22bfloat162_rn(make_float2(x, y));
    return *reinterpret_cast<unsigned*>(&h);
}
__device__ __forceinline__ float2 unpackbf(unsigned u) {
    __nv_bfloat162 h = *reinterpret_cast<__nv_bfloat162*>(&u);
    return __bfloat1622float2(h);
}
__device__ __forceinline__ void splitpair(float x, float y,
                                          unsigned& hi, unsigned& lo) {
    hi = packbf(x, y);
    float2 h = unpackbf(hi);
    lo = packbf(x - h.x, y - h.y);
}
__device__ __forceinline__ uint32_t smem_u32(const void* p) {
    uint32_t a;
    asm("{ .reg .u64 t; cvta.to.shared.u64 t, %1; cvt.u32.u64 %0, t; }"
        : "=r"(a) : "l"(p));
    return a;
}

#define LDSM4(d0, d1, d2, d3, a) \
    asm volatile("ldmatrix.sync.aligned.m8n8.x4.shared.b16 {%0,%1,%2,%3}, [%4];" \
                 : "=r"(d0), "=r"(d1), "=r"(d2), "=r"(d3) : "r"(a))

#define CP16(dst, src) \
    asm volatile("cp.async.cg.shared.global [%0], [%1], 16;" :: "r"(dst), "l"(src))
#define CP_COMMIT() asm volatile("cp.async.commit_group;" ::: "memory")
#define CP_WAIT1()  asm volatile("cp.async.wait_group 1;" ::: "memory")
#define CP_WAIT0()  asm volatile("cp.async.wait_group 0;" ::: "memory")

__device__ __forceinline__ void mma_bf16(float c[4],
                                         unsigned a0, unsigned a1, unsigned a2, unsigned a3,
                                         unsigned b0, unsigned b1) {
    asm volatile(
        "mma.sync.aligned.m16n8k16.row.col.f32.bf16.bf16.f32 "
        "{%0,%1,%2,%3}, {%4,%5,%6,%7}, {%8,%9}, {%0,%1,%2,%3};"
        : "+f"(c[0]), "+f"(c[1]), "+f"(c[2]), "+f"(c[3])
        : "r"(a0), "r"(a1), "r"(a2), "r"(a3), "r"(b0), "r"(b1));
}
__device__ __forceinline__ void mma3(float c[4],
                                     const unsigned ah[4], const unsigned al[4],
                                     unsigned bh0, unsigned bh1,
                                     unsigned bl0, unsigned bl1) {
    mma_bf16(c, ah[0], ah[1], ah[2], ah[3], bh0, bh1);
    mma_bf16(c, ah[0], ah[1], ah[2], ah[3], bl0, bl1);
    mma_bf16(c, al[0], al[1], al[2], al[3], bh0, bh1);
}

// ---------------------------------------------------------------------------
// split kernel: z 0..2 -> X (Q,K,V inputs), z 3..6 -> W (Wq,Wk,Wv,Wo)
// ---------------------------------------------------------------------------
__global__ __launch_bounds__(256)
void split_kernel(const float* __restrict__ Q, const float* __restrict__ K,
                  const float* __restrict__ V,
                  const float* __restrict__ Wq, const float* __restrict__ Wk,
                  const float* __restrict__ Wv, const float* __restrict__ Wo)
{
    const int z = blockIdx.z;
    const float* src;
    unsigned *dh, *dl;
    int n;
    if (z < 3) {
        src = (z == 0) ? Q : (z == 1) ? K : V;
        dh = g_xh + (size_t)z * XW;
        dl = g_xl + (size_t)z * XW;
        n = MROWS * DMODEL;
    } else {
        src = (z == 3) ? Wq : (z == 4) ? Wk : (z == 5) ? Wv : Wo;
        dh = g_wh + (size_t)(z - 3) * WW;
        dl = g_wl + (size_t)(z - 3) * WW;
        n = DMODEL * DMODEL;
    }
    const int i8 = (blockIdx.x * 256 + threadIdx.x) * 8;
    if (i8 >= n) return;
    float4 a = *(const float4*)(src + i8);
    float4 b = *(const float4*)(src + i8 + 4);
    unsigned h0, l0, h1, l1, h2, l2, h3, l3;
    splitpair(a.x, a.y, h0, l0);
    splitpair(a.z, a.w, h1, l1);
    splitpair(b.x, b.y, h2, l2);
    splitpair(b.z, b.w, h3, l3);
    *(uint4*)(dh + (i8 >> 1)) = make_uint4(h0, h1, h2, h3);
    *(uint4*)(dl + (i8 >> 1)) = make_uint4(l0, l1, l2, l3);
}

// ---------------------------------------------------------------------------
// GEMM: C[2048,1024] = A @ W^T (+bias). Operands planar hi/lo bf16 (words).
// CTA 128x128, 8 warps 2x4 (warp 64x32), BK=32, 2-stage cp.async.
// SMEM per stage: Ah,Al,Wh,Wl each 128 rows x 80B (row = 32 bf16 + pad).
// Row stride 80B -> 8-row LDSM phases hit distinct 16B banks (mod 128B).
// ---------------------------------------------------------------------------
#define ARRB  (128 * 80)             // 10240 B per array
#define STAGE (4 * ARRB)             // 40960 B
#define SMEM_DYN (2 * STAGE)         // 81920 B

__device__ __forceinline__ void stage_arr(uint32_t dst, const unsigned* srcW,
                                          int rowBase, int kWord, int tid)
{
#pragma unroll
    for (int i = 0; i < 2; i++) {
        const int task = tid + i * 256;          // 0..511
        const int row = task >> 2, v = task & 3;
        const unsigned* s = srcW + (size_t)(rowBase + row) * 512 + kWord + v * 4;
        CP16(dst + row * 80 + v * 16, s);
    }
}

template <bool SPLIT_OUT>
__device__ __forceinline__ void gemm_body(const unsigned* __restrict__ Ahw,
                                          const unsigned* __restrict__ Alw,
                                          const unsigned* __restrict__ Whw,
                                          const unsigned* __restrict__ Wlw,
                                          const float* __restrict__ bias,
                                          float* __restrict__ C,
                                          unsigned* __restrict__ Ch,
                                          unsigned* __restrict__ Cl)
{
    extern __shared__ char smem[];
    const uint32_t su = smem_u32(smem);
    const int tid  = threadIdx.x;
    const int warp = tid >> 5;
    const int lane = tid & 31;
    const int g    = lane >> 2;
    const int q    = lane & 3;
    const int wrow = (warp >> 2) * 64;
    const int wcol = (warp & 3) * 32;
    const int byBase = blockIdx.y * 128;
    const int bxBase = blockIdx.x * 128;

    // ldmatrix per-lane source selectors
    const int r   = lane & 7;
    const int sel = lane >> 3;
    const int aRow = r + ((sel & 1) ? 8 : 0);    // A: groups 1,3 -> +8 rows
    const int aK   = (sel >> 1) ? 16 : 0;        // A: groups 2,3 -> +8 halves (16B)
    const int bRow = r + ((sel >> 1) ? 8 : 0);   // B: groups 2,3 -> +8 rows
    const int bK   = (sel & 1) ? 16 : 0;         // B: groups 1,3 -> +8 halves

    auto issue = [&](int chunk) {
        const uint32_t sb = su + (chunk & 1) * STAGE;
        const int kWord = chunk * 16;            // 32 halves per chunk
        stage_arr(sb,            Ahw, byBase, kWord, tid);
        stage_arr(sb + ARRB,     Alw, byBase, kWord, tid);
        stage_arr(sb + 2 * ARRB, Whw, bxBase, kWord, tid);
        stage_arr(sb + 3 * ARRB, Wlw, bxBase, kWord, tid);
        CP_COMMIT();
    };

    float acc[4][4][4];
#pragma unroll
    for (int mt = 0; mt < 4; mt++)
#pragma unroll
        for (int nt = 0; nt < 4; nt++)
#pragma unroll
            for (int e = 0; e < 4; e++) acc[mt][nt][e] = 0.f;

    issue(0);
    issue(1);

    for (int c = 0; c < 32; c++) {
        if (c + 2 < 32) { CP_WAIT1(); } else { CP_WAIT0(); }
        __syncthreads();
        const uint32_t sb = su + (c & 1) * STAGE;

#pragma unroll
        for (int ks = 0; ks < 2; ks++) {
            const int kB = ks * 32;              // byte offset of k16 step
            unsigned ah[4][4], al[4][4];
#pragma unroll
            for (int mt = 0; mt < 4; mt++) {
                const uint32_t ra = sb + (wrow + mt * 16 + aRow) * 80 + kB + aK;
                LDSM4(ah[mt][0], ah[mt][1], ah[mt][2], ah[mt][3], ra);
                LDSM4(al[mt][0], al[mt][1], al[mt][2], al[mt][3], ra + ARRB);
            }
            unsigned wbh[4][2], wbl[4][2];
#pragma unroll
            for (int p = 0; p < 2; p++) {
                const uint32_t rb = sb + 2 * ARRB + (wcol + p * 16 + bRow) * 80 + kB + bK;
                unsigned t0, t1, t2, t3;
                LDSM4(t0, t1, t2, t3, rb);
                wbh[2 * p][0] = t0; wbh[2 * p][1] = t1;
                wbh[2 * p + 1][0] = t2; wbh[2 * p + 1][1] = t3;
                LDSM4(t0, t1, t2, t3, rb + ARRB);
                wbl[2 * p][0] = t0; wbl[2 * p][1] = t1;
                wbl[2 * p + 1][0] = t2; wbl[2 * p + 1][1] = t3;
            }
#pragma unroll
            for (int nt = 0; nt < 4; nt++)
#pragma unroll
                for (int mt = 0; mt < 4; mt++)
                    mma3(acc[mt][nt], ah[mt], al[mt],
                         wbh[nt][0], wbh[nt][1], wbl[nt][0], wbl[nt][1]);
        }
        __syncthreads();
        if (c + 2 < 32) issue(c + 2);
    }

    // epilogue: c0,c1 = (row g, cols 2q,2q+1); c2,c3 = (row g+8, same)
#pragma unroll
    for (int nt = 0; nt < 4; nt++) {
        const int col = bxBase + wcol + nt * 8 + 2 * q;
        const float2 bb = *(const float2*)&bias[col];
#pragma unroll
        for (int mt = 0; mt < 4; mt++) {
            const int row = byBase + wrow + mt * 16 + g;
            if (SPLIT_OUT) {
                const size_t w0 = (size_t)row * 512 + (col >> 1);
                const size_t w1 = (size_t)(row + 8) * 512 + (col >> 1);
                unsigned hh, ll;
                splitpair(acc[mt][nt][0] + bb.x, acc[mt][nt][1] + bb.y, hh, ll);
                Ch[w0] = hh; Cl[w0] = ll;
                splitpair(acc[mt][nt][2] + bb.x, acc[mt][nt][3] + bb.y, hh, ll);
                Ch[w1] = hh; Cl[w1] = ll;
            } else {
                *(float2*)&C[(size_t)row * DMODEL + col] =
                    make_float2(acc[mt][nt][0] + bb.x, acc[mt][nt][1] + bb.y);
                *(float2*)&C[(size_t)(row + 8) * DMODEL + col] =
                    make_float2(acc[mt][nt][2] + bb.x, acc[mt][nt][3] + bb.y);
            }
        }
    }
}

__global__ __launch_bounds__(256)
void qkv_gemm(const float* __restrict__ bq, const float* __restrict__ bk,
              const float* __restrict__ bv)
{
    const int z = blockIdx.z;
    const unsigned* Ahw = g_xh + (size_t)z * XW;
    const unsigned* Alw = g_xl + (size_t)z * XW;
    const unsigned* Whw = g_wh + (size_t)z * WW;
    const unsigned* Wlw = g_wl + (size_t)z * WW;
    const float* bias = (z == 0) ? bq : (z == 1) ? bk : bv;
    unsigned* Ch = (z == 0) ? g_qh : (z == 1) ? g_kh : g_vh;
    unsigned* Cl = (z == 0) ? g_ql : (z == 1) ? g_kl : g_vl;
    gemm_body<true>(Ahw, Alw, Whw, Wlw, bias, nullptr, Ch, Cl);
}

__global__ __launch_bounds__(256)
void out_gemm(const float* __restrict__ bo, float* __restrict__ out)
{
    gemm_body<false>(g_ch, g_cl, g_wh + (size_t)3 * WW, g_wl + (size_t)3 * WW,
                     bo, out, nullptr, nullptr);
}

// ---------------------------------------------------------------------------
// Attention: grid (S/256, 64, 2), 256 thr, warp = 32 q rows, key tiles of 64,
// single-pass softmax (scale folded into exp). Pre-split operands; ldmatrix
// B-fragments. ctx written split bf16.
// ---------------------------------------------------------------------------
#define KT 64

__global__ __launch_bounds__(256)
void attn_kernel()
{
    const int h    = blockIdx.y;
    const int b    = blockIdx.z;
    const int tid  = threadIdx.x;
    const int warp = tid >> 5;
    const int lane = tid & 31;
    const int g    = lane >> 2;
    const int q    = lane & 3;

    // K: [key][word] stride 12 words (48B) -> LDSM conflict-free
    __shared__ __align__(16) unsigned Kh[KT][12], Kl[KT][12];
    // V^T: [e][key-pair] stride 36 words (144B) -> LDSM conflict-free
    __shared__ __align__(16) unsigned Vth[EDIM][36], Vtl[EDIM][36];

    const int hw   = h * 8;                    // head offset in words
    const size_t bRow = (size_t)b * SEQ;

    // ldmatrix selectors (B-frag pattern)
    const int r    = lane & 7;
    const int sel  = lane >> 3;
    const int bRw  = r + ((sel >> 1) ? 8 : 0);
    const int bWo  = (sel & 1) ? 4 : 0;        // word offset

    // ---- Q fragments from pre-split g_qh/g_ql ----
    const int rowBase = blockIdx.x * 256 + warp * 32;
    unsigned qh[2][4], ql[2][4];
#pragma unroll
    for (int mt = 0; mt < 2; mt++) {
        const size_t r0 = bRow + rowBase + mt * 16 + g;
        const size_t w0 = r0 * 512 + hw;
        const size_t w1 = (r0 + 8) * 512 + hw;
        qh[mt][0] = g_qh[w0 + q];     ql[mt][0] = g_ql[w0 + q];
        qh[mt][1] = g_qh[w1 + q];     ql[mt][1] = g_ql[w1 + q];
        qh[mt][2] = g_qh[w0 + 4 + q]; ql[mt][2] = g_ql[w0 + 4 + q];
        qh[mt][3] = g_qh[w1 + 4 + q]; ql[mt][3] = g_ql[w1 + 4 + q];
    }

    float oacc[2][2][4];
#pragma unroll
    for (int mt = 0; mt < 2; mt++)
#pragma unroll
        for (int ne = 0; ne < 2; ne++)
#pragma unroll
            for (int e = 0; e < 4; e++) oacc[mt][ne][e] = 0.f;
    float lsum[2][2] = {{0.f, 0.f}, {0.f, 0.f}};

    for (int kt = 0; kt < SEQ; kt += KT) {
        // ---- stage K tile (pure word copies from pre-split) ----
        {
            const int key  = tid >> 2;
            const int quad = tid & 3;
            const size_t wsrc = (bRow + kt + key) * 512 + hw + 2 * quad;
            *(uint2*)&Kh[key][2 * quad] = *(const uint2*)&g_kh[wsrc];
            *(uint2*)&Kl[key][2 * quad] = *(const uint2*)&g_kl[wsrc];
        }
        // ---- stage V^T: word (e, kp) = halves (v[2kp][e], v[2kp+1][e]) ----
        {
            const int e  = tid & 15;
            const int k0 = tid >> 4;
            const unsigned short* vhh = (const unsigned short*)g_vh;
            const unsigned short* vll = (const unsigned short*)g_vl;
#pragma unroll
            for (int rep = 0; rep < 2; rep++) {
                const int kp = k0 + rep * 16;
                const size_t h0 = (bRow + kt + 2 * kp) * 1024 + hw * 2 + e;
                const size_t h1 = h0 + 1024;
                Vth[e][kp] = (unsigned)vhh[h0] | ((unsigned)vhh[h1] << 16);
                Vtl[e][kp] = (unsigned)vll[h0] | ((unsigned)vll[h1] << 16);
            }
        }
        __syncthreads();

        // ---- QK^T B-fragments via ldmatrix ----
        unsigned kbh[8][2], kbl[8][2];
#pragma unroll
        for (int p = 0; p < 4; p++) {
            unsigned t0, t1, t2, t3;
            LDSM4(t0, t1, t2, t3, smem_u32(&Kh[p * 16 + bRw][bWo]));
            kbh[2 * p][0] = t0; kbh[2 * p][1] = t1;
            kbh[2 * p + 1][0] = t2; kbh[2 * p + 1][1] = t3;
            LDSM4(t0, t1, t2, t3, smem_u32(&Kl[p * 16 + bRw][bWo]));
            kbl[2 * p][0] = t0; kbl[2 * p][1] = t1;
            kbl[2 * p + 1][0] = t2; kbl[2 * p + 1][1] = t3;
        }

        float s[2][8][4];
#pragma unroll
        for (int mt = 0; mt < 2; mt++)
#pragma unroll
            for (int nt = 0; nt < 8; nt++)
#pragma unroll
                for (int e = 0; e < 4; e++) s[mt][nt][e] = 0.f;

#pragma unroll
        for (int nt = 0; nt < 8; nt++)
#pragma unroll
            for (int mt = 0; mt < 2; mt++)
                mma3(s[mt][nt], qh[mt], ql[mt],
                     kbh[nt][0], kbh[nt][1], kbl[nt][0], kbl[nt][1]);

        // ---- exp (scale 1/32 folded) + row sums ----
#pragma unroll
        for (int mt = 0; mt < 2; mt++)
#pragma unroll
            for (int nt = 0; nt < 8; nt++) {
                float p0 = __expf(s[mt][nt][0] * 0.03125f);
                float p1 = __expf(s[mt][nt][1] * 0.03125f);
                float p2 = __expf(s[mt][nt][2] * 0.03125f);
                float p3 = __expf(s[mt][nt][3] * 0.03125f);
                s[mt][nt][0] = p0; s[mt][nt][1] = p1;
                s[mt][nt][2] = p2; s[mt][nt][3] = p3;
                lsum[mt][0] += p0 + p1;
                lsum[mt][1] += p2 + p3;
            }

        // ---- P.V: register repack + ldmatrix V^T B-frags ----
#pragma unroll
        for (int kt2 = 0; kt2 < 4; kt2++) {
            unsigned pah[2][4], pal[2][4];
#pragma unroll
            for (int mt = 0; mt < 2; mt++) {
                splitpair(s[mt][2 * kt2][0], s[mt][2 * kt2][1], pah[mt][0], pal[mt][0]);
                splitpair(s[mt][2 * kt2][2], s[mt][2 * kt2][3], pah[mt][1], pal[mt][1]);
                splitpair(s[mt][2 * kt2 + 1][0], s[mt][2 * kt2 + 1][1], pah[mt][2], pal[mt][2]);
                splitpair(s[mt][2 * kt2 + 1][2], s[mt][2 * kt2 + 1][3], pah[mt][3], pal[mt][3]);
            }
            unsigned vbh[2][2], vbl[2][2];
            {
                unsigned t0, t1, t2, t3;
                LDSM4(t0, t1, t2, t3, smem_u32(&Vth[bRw][kt2 * 8 + bWo]));
                vbh[0][0] = t0; vbh[0][1] = t1; vbh[1][0] = t2; vbh[1][1] = t3;
                LDSM4(t0, t1, t2, t3, smem_u32(&Vtl[bRw][kt2 * 8 + bWo]));
                vbl[0][0] = t0; vbl[0][1] = t1; vbl[1][0] = t2; vbl[1][1] = t3;
            }
#pragma unroll
            for (int ne = 0; ne < 2; ne++)
#pragma unroll
                for (int mt = 0; mt < 2; mt++)
                    mma3(oacc[mt][ne], pah[mt], pal[mt],
                         vbh[ne][0], vbh[ne][1], vbl[ne][0], vbl[ne][1]);
        }
        __syncthreads();
    }

    // ---- finalize: quad-reduce sums, normalize, store split ctx ----
#pragma unroll
    for (int mt = 0; mt < 2; mt++)
#pragma unroll
        for (int rr = 0; rr < 2; rr++) {
            float v = lsum[mt][rr];
            v += __shfl_xor_sync(0xFFFFFFFF, v, 1);
            v += __shfl_xor_sync(0xFFFFFFFF, v, 2);
            lsum[mt][rr] = 1.0f / v;
        }

#pragma unroll
    for (int mt = 0; mt < 2; mt++) {
        const size_t r0 = bRow + rowBase + mt * 16 + g;
#pragma unroll
        for (int ne = 0; ne < 2; ne++) {
            const int colw = ne * 4 + q;       // word within head
            const size_t w0 = r0 * 512 + hw + colw;
            const size_t w1 = (r0 + 8) * 512 + hw + colw;
            unsigned hh, ll;
            splitpair(oacc[mt][ne][0] * lsum[mt][0], oacc[mt][ne][1] * lsum[mt][0], hh, ll);
            g_ch[w0] = hh; g_cl[w0] = ll;
            splitpair(oacc[mt][ne][2] * lsum[mt][1], oacc[mt][ne][3] * lsum[mt][1], hh, ll);
            g_ch[w1] = hh; g_cl[w1] = ll;
        }
    }
}

// ---------------------------------------------------------------------------
// kernel_launch: inputs 0:Q 1:K 2:V 3:Wq 4:bq 5:Wk 6:bk 7:Wv 8:bv 9:Wo 10:bo
// ---------------------------------------------------------------------------
extern "C" void kernel_launch(void* const* d_in, const int* in_sizes, int n_in,
                              void* d_out, int out_size)
{
    (void)in_sizes; (void)n_in; (void)out_size;
    const float* Q  = (const float*)d_in[0];
    const float* K  = (const float*)d_in[1];
    const float* V  = (const float*)d_in[2];
    const float* Wq = (const float*)d_in[3];
    const float* bq = (const float*)d_in[4];
    const float* Wk = (const float*)d_in[5];
    const float* bk = (const float*)d_in[6];
    const float* Wv = (const float*)d_in[7];
    const float* bv = (const float*)d_in[8];
    const float* Wo = (const float*)d_in[9];
    const float* bo = (const float*)d_in[10];
    float* out = (float*)d_out;

    cudaFuncSetAttribute(qkv_gemm, cudaFuncAttributeMaxDynamicSharedMemorySize, SMEM_DYN);
    cudaFuncSetAttribute(out_gemm, cudaFuncAttributeMaxDynamicSharedMemorySize, SMEM_DYN);

    dim3 gsplit(1024, 1, 7);
    split_kernel<<<gsplit, 256>>>(Q, K, V, Wq, Wk, Wv, Wo);

    dim3 gqkv(DMODEL / 128, MROWS / 128, 3);   // (8, 16, 3)
    qkv_gemm<<<gqkv, 256, SMEM_DYN>>>(bq, bk, bv);

    dim3 gattn(SEQ / 256, NHEADS, BDIM);       // (4, 64, 2)
    attn_kernel<<<gattn, 256>>>();

    dim3 gout(DMODEL / 128, MROWS / 128);      // (8, 16)
    out_gemm<<<gout, 256, SMEM_DYN>>>(bo, out);
}